// round 1
// baseline (speedup 1.0000x reference)
#include <cuda_runtime.h>
#include <cstdint>

#define Sdim 2048
#define Bdim 32
#define Hdim 512
#define Gdim 2048   // 4*H
#define NCTA_REC 128
#define THR_REC 128

// Scratch (module-load allocated, not counted against run-time alloc guards)
__device__ float g_xg [(size_t)Sdim * Bdim * Gdim];   // [s][b][4H]  512 MB
__device__ float g_h1s[(size_t)Sdim * Bdim * Hdim];   // layer-1 hidden seq, [s][b][H] 128 MB
__device__ float g_hbuf[2][Bdim * Hdim];              // ping-pong h(t)
__device__ unsigned g_cnt;
__device__ unsigned g_gen;

// ---------------- grid barrier (sense-reversal, replay-safe) ----------------
__device__ __forceinline__ void grid_barrier() {
    __syncthreads();
    if (threadIdx.x == 0) {
        __threadfence();
        unsigned gen = *(volatile unsigned*)&g_gen;
        unsigned old = atomicAdd(&g_cnt, 1u);
        if (old == gridDim.x - 1) {
            atomicExch(&g_cnt, 0u);
            __threadfence();
            atomicAdd(&g_gen, 1u);
        } else {
            while (*(volatile unsigned*)&g_gen == gen) { __nanosleep(32); }
        }
        __threadfence();
    }
    __syncthreads();
}

// ---------------- input projection GEMM ----------------
// C[row=(s*B+b)][g] = sum_k A[row][k] * W[g][k] + bih[g] + bhh[g]
// layer0: A row (s,b) -> X[b][s][:] ; else g_h1s[row][:]
__global__ __launch_bounds__(256) void gemm_xg_kernel(
    const float* __restrict__ X, const float* __restrict__ W,
    const float* __restrict__ bih, const float* __restrict__ bhh, int layer0)
{
    __shared__ float As[8 * 128];
    __shared__ float Bs[8 * 128];
    int tid  = threadIdx.x;
    int row0 = blockIdx.y * 128;
    int col0 = blockIdx.x * 128;

    int arow = tid >> 1;
    int akq  = (tid & 1) * 4;
    int grow = row0 + arow;
    const float* Abase;
    if (layer0) {
        int b = grow & 31, s = grow >> 5;
        Abase = X + ((size_t)b * Sdim + s) * Hdim;
    } else {
        Abase = g_h1s + (size_t)grow * Hdim;
    }
    const float* Wbase = W + (size_t)(col0 + arow) * Hdim;

    int tx = tid & 15, ty = tid >> 4;
    float acc[8][8];
#pragma unroll
    for (int i = 0; i < 8; i++)
#pragma unroll
        for (int j = 0; j < 8; j++) acc[i][j] = 0.0f;

    for (int k0 = 0; k0 < Hdim; k0 += 8) {
        float4 av = *(const float4*)(Abase + k0 + akq);
        float4 wv = *(const float4*)(Wbase + k0 + akq);
        As[(akq + 0) * 128 + arow] = av.x;
        As[(akq + 1) * 128 + arow] = av.y;
        As[(akq + 2) * 128 + arow] = av.z;
        As[(akq + 3) * 128 + arow] = av.w;
        Bs[(akq + 0) * 128 + arow] = wv.x;
        Bs[(akq + 1) * 128 + arow] = wv.y;
        Bs[(akq + 2) * 128 + arow] = wv.z;
        Bs[(akq + 3) * 128 + arow] = wv.w;
        __syncthreads();
#pragma unroll
        for (int kk = 0; kk < 8; kk++) {
            float4 a0 = *(const float4*)&As[kk * 128 + ty * 8];
            float4 a1 = *(const float4*)&As[kk * 128 + ty * 8 + 4];
            float4 b0 = *(const float4*)&Bs[kk * 128 + tx * 8];
            float4 b1 = *(const float4*)&Bs[kk * 128 + tx * 8 + 4];
            float a[8] = {a0.x, a0.y, a0.z, a0.w, a1.x, a1.y, a1.z, a1.w};
            float b[8] = {b0.x, b0.y, b0.z, b0.w, b1.x, b1.y, b1.z, b1.w};
#pragma unroll
            for (int i = 0; i < 8; i++)
#pragma unroll
                for (int j = 0; j < 8; j++) acc[i][j] += a[i] * b[j];
        }
        __syncthreads();
    }

    float bias[8];
#pragma unroll
    for (int j = 0; j < 8; j++) {
        int col = col0 + tx * 8 + j;
        bias[j] = __ldg(&bih[col]) + __ldg(&bhh[col]);
    }
#pragma unroll
    for (int i = 0; i < 8; i++) {
        float* crow = g_xg + (size_t)(row0 + ty * 8 + i) * Gdim + col0 + tx * 8;
#pragma unroll
        for (int j = 0; j < 8; j++) crow[j] = acc[i][j] + bias[j];
    }
}

// ---------------- persistent recurrence ----------------
// 128 CTAs x 128 threads. CTA owns hidden units j0..j0+3 (all 4 gates, all 32 b).
// Thread (jj, b): computes i,f,g,o dots for hidden j0+jj, batch b; keeps c in reg.
__global__ __launch_bounds__(THR_REC, 1) void lstm_recur_kernel(
    const float* __restrict__ Whh, float* __restrict__ hseq,
    int out_bsh, float* __restrict__ hTo, float* __restrict__ cTo)
{
    extern __shared__ float sm[];
    float* Wsm = sm;                 // [16][512]  rows r = q*4+jj
    float* hsm = sm + 16 * Hdim;     // [32][516]  padded

    int tid = threadIdx.x;
    int b  = tid & 31;
    int jj = tid >> 5;
    int j0 = blockIdx.x * 4;

    // stage Whh rows for this CTA (reused all 2048 steps)
    for (int idx = tid; idx < 16 * 128; idx += THR_REC) {
        int r = idx >> 7, kq = (idx & 127) * 4;
        int q = r >> 2, j = r & 3;
        float4 v = *(const float4*)(Whh + (size_t)(q * Hdim + j0 + j) * Hdim + kq);
        *(float4*)&Wsm[r * Hdim + kq] = v;
    }
    // h(0) = 0 (each CTA zeros its slice; union covers all of hbuf[0])
    g_hbuf[0][b * Hdim + j0 + jj] = 0.0f;
    float c = 0.0f;
    grid_barrier();

    const float*  xg_t = g_xg + (size_t)b * Gdim + (j0 + jj);
    const float4* wi4  = (const float4*)&Wsm[(0 * 4 + jj) * Hdim];
    const float4* wf4  = (const float4*)&Wsm[(1 * 4 + jj) * Hdim];
    const float4* wg4  = (const float4*)&Wsm[(2 * 4 + jj) * Hdim];
    const float4* wo4  = (const float4*)&Wsm[(3 * 4 + jj) * Hdim];
    const float4* hrow = (const float4*)&hsm[b * 516];

    for (int t = 0; t < Sdim; t++) {
        int cur = t & 1;
        // prefetch this step's xg early (hide L2 latency under the smem copy)
        float xi  = __ldg(xg_t + 0 * Hdim);
        float xf  = __ldg(xg_t + 1 * Hdim);
        float xgg = __ldg(xg_t + 2 * Hdim);
        float xo  = __ldg(xg_t + 3 * Hdim);

        // stage h(t-1): global [b][k] -> smem [b][516] (L1 bypass: written last step)
        const float4* src = (const float4*)g_hbuf[cur];
#pragma unroll
        for (int i = 0; i < 32; i++) {
            int idx = tid + i * THR_REC;
            float4 v = __ldcg(src + idx);
            int bb = idx >> 7, kq = idx & 127;
            *(float4*)&hsm[bb * 516 + kq * 4] = v;
        }
        __syncthreads();

        float ai = 0.f, af = 0.f, ag = 0.f, ao = 0.f;
#pragma unroll 4
        for (int kq = 0; kq < 128; kq++) {
            float4 h4 = hrow[kq];
            float4 w;
            w = wi4[kq]; ai += w.x*h4.x + w.y*h4.y + w.z*h4.z + w.w*h4.w;
            w = wf4[kq]; af += w.x*h4.x + w.y*h4.y + w.z*h4.z + w.w*h4.w;
            w = wg4[kq]; ag += w.x*h4.x + w.y*h4.y + w.z*h4.z + w.w*h4.w;
            w = wo4[kq]; ao += w.x*h4.x + w.y*h4.y + w.z*h4.z + w.w*h4.w;
        }
        ai += xi; af += xf; ag += xgg; ao += xo;

        float ig = 1.0f / (1.0f + __expf(-ai));
        float fg = 1.0f / (1.0f + __expf(-af));
        float gg = tanhf(ag);
        float og = 1.0f / (1.0f + __expf(-ao));
        c = fg * c + ig * gg;
        float h = og * tanhf(c);

        g_hbuf[cur ^ 1][b * Hdim + j0 + jj] = h;
        if (out_bsh) {
            hseq[((size_t)b * Sdim + t) * Hdim + j0 + jj] = h;   // ht[b][s][h]
        } else {
            g_h1s[((size_t)t * Bdim + b) * Hdim + j0 + jj] = h;  // [s][b][h] for next GEMM
        }
        if (hTo && t == Sdim - 1) {
            hTo[b * Hdim + j0 + jj] = h;
            cTo[b * Hdim + j0 + jj] = c;
        }
        xg_t += (size_t)Bdim * Gdim;
        grid_barrier();
    }
}

// ---------------- launch ----------------
extern "C" void kernel_launch(void* const* d_in, const int* in_sizes, int n_in,
                              void* d_out, int out_size) {
    (void)in_sizes; (void)n_in;
    const float* X   = (const float*)d_in[0];
    const float* Wih = (const float*)d_in[1];
    const float* Whh = (const float*)d_in[2];
    const float* bih = (const float*)d_in[3];
    const float* bhh = (const float*)d_in[4];
    float* out = (float*)d_out;

    size_t ht_elems = (size_t)Bdim * Sdim * Hdim;
    float* hTo = nullptr; float* cTo = nullptr;
    if ((size_t)out_size >= ht_elems + 2 * (size_t)Bdim * Hdim) {
        hTo = out + ht_elems;
        cTo = hTo + (size_t)Bdim * Hdim;
    }

    const int smem_rec = (16 * Hdim + 32 * 516) * 4;  // 98816 B
    cudaFuncSetAttribute(lstm_recur_kernel,
                         cudaFuncAttributeMaxDynamicSharedMemorySize, smem_rec);

    dim3 ggrid(Gdim / 128, (Sdim * Bdim) / 128);  // (16, 512)

    // Layer 0
    gemm_xg_kernel<<<ggrid, 256>>>(X, Wih, bih, bhh, 1);
    lstm_recur_kernel<<<NCTA_REC, THR_REC, smem_rec>>>(Whh, nullptr, 0, nullptr, nullptr);
    // Layer 1
    gemm_xg_kernel<<<ggrid, 256>>>(X, Wih + (size_t)Gdim * Hdim,
                                   bih + Gdim, bhh + Gdim, 0);
    lstm_recur_kernel<<<NCTA_REC, THR_REC, smem_rec>>>(Whh + (size_t)Gdim * Hdim,
                                                       out, 1, hTo, cTo);
}